// round 14
// baseline (speedup 1.0000x reference)
#include <cuda_runtime.h>
#include <cuda_bf16.h>
#include <cstdint>
#include <cstddef>

#define T_SEQ 512
#define BATCH 64
#define NTOK  (BATCH * T_SEQ)   // 32768
#define NB 2                    // batches per GRU cluster
#define QH 40                   // hidden units / k-range per CTA (160/4)

typedef unsigned long long ull;

// ---- packed f32x2 helpers (sm_103a FFMA2 path) -----------------------------
__device__ __forceinline__ void fma2(ull& d, ull a, ull b) {
    asm("fma.rn.f32x2 %0, %1, %2, %0;" : "+l"(d) : "l"(a), "l"(b));
}
__device__ __forceinline__ ull pk2(float lo, float hi) {
    ull d; asm("mov.b64 %0, {%1, %2};" : "=l"(d) : "f"(lo), "f"(hi)); return d;
}
__device__ __forceinline__ float2 upk2(ull v) {
    float2 r; asm("mov.b64 {%0, %1}, %2;" : "=f"(r.x), "=f"(r.y) : "l"(v)); return r;
}
__device__ __forceinline__ float hsum2(ull v) {
    float2 e = upk2(v); return e.x + e.y;
}

// ----------------------------- scratch ------------------------------------
__device__ float g_xw[(size_t)NTOK * 960];
__device__ float g_h1[(size_t)NTOK * 320];
__device__ float g_seq[(size_t)NTOK * 320];
__device__ float g_keys[(size_t)NTOK * 160];
__device__ float g_logits[(size_t)NTOK * 4];
__device__ float g_motion[NTOK];
__device__ float g_pooled[BATCH * 320];

// bf16 hi/lo staging buffers (A: up to 32768x320; W: all three weights packed)
__device__ __nv_bfloat16 g_ahi[(size_t)NTOK * 320];
__device__ __nv_bfloat16 g_alo[(size_t)NTOK * 320];
#define OFF_W0 0
#define OFF_W1 (960 * 128)
#define OFF_KW (960 * 128 + 960 * 320)
#define W_TOTAL (960 * 128 + 960 * 320 + 160 * 320)
__device__ __nv_bfloat16 g_whi[W_TOTAL];
__device__ __nv_bfloat16 g_wlo[W_TOTAL];

// -------------------- fp32 -> bf16 hi/lo split kernel ----------------------
__global__ void __launch_bounds__(256) split_kernel(
    const float4* __restrict__ src, uint2* __restrict__ hi,
    uint2* __restrict__ lo, int n4)
{
    int i = blockIdx.x * blockDim.x + threadIdx.x;
    if (i >= n4) return;
    float4 v = src[i];
    __nv_bfloat16 hx = __float2bfloat16(v.x), hy = __float2bfloat16(v.y);
    __nv_bfloat16 hz = __float2bfloat16(v.z), hw = __float2bfloat16(v.w);
    __nv_bfloat16 lx = __float2bfloat16(v.x - __bfloat162float(hx));
    __nv_bfloat16 ly = __float2bfloat16(v.y - __bfloat162float(hy));
    __nv_bfloat16 lz = __float2bfloat16(v.z - __bfloat162float(hz));
    __nv_bfloat16 lw = __float2bfloat16(v.w - __bfloat162float(hw));
    __nv_bfloat162 h01; h01.x = hx; h01.y = hy;
    __nv_bfloat162 h23; h23.x = hz; h23.y = hw;
    __nv_bfloat162 l01; l01.x = lx; l01.y = ly;
    __nv_bfloat162 l23; l23.x = lz; l23.y = lw;
    uint2 ho, loo;
    ho.x  = *reinterpret_cast<uint32_t*>(&h01);
    ho.y  = *reinterpret_cast<uint32_t*>(&h23);
    loo.x = *reinterpret_cast<uint32_t*>(&l01);
    loo.y = *reinterpret_cast<uint32_t*>(&l23);
    hi[i] = ho;
    lo[i] = loo;
}

// ================= HMMA (mma.sync) bf16-compensated GEMM ===================
// Inputs pre-split to bf16 hi/lo. C = Ahi*Bhi + Ahi*Blo + Alo*Bhi + bias(+tanh)
// CTA tile 128x128, 8 warps (2x4) of 64x32 warp tiles, K chunked by 32,
// double-buffered smem staging (pure LDG->STS, no conversion in loop).

#define GSTR 40               // bf16 elements per smem row (80B stride)
#define CHELEM (128 * GSTR)   // 5120 bf16 per array per buffer
#define GEMM_SMEM (8 * CHELEM * (int)sizeof(__nv_bfloat16))   // 81920 B

__device__ __forceinline__ void mma_bf16(float* c, const uint32_t* a, const uint32_t* b) {
    asm volatile(
        "mma.sync.aligned.m16n8k16.row.col.f32.bf16.bf16.f32 "
        "{%0,%1,%2,%3}, {%4,%5,%6,%7}, {%8,%9}, {%0,%1,%2,%3};"
        : "+f"(c[0]), "+f"(c[1]), "+f"(c[2]), "+f"(c[3])
        : "r"(a[0]), "r"(a[1]), "r"(a[2]), "r"(a[3]), "r"(b[0]), "r"(b[1]));
}

__global__ void __launch_bounds__(256, 2) mma_gemm_bias(
    const __nv_bfloat16* __restrict__ Ahi, const __nv_bfloat16* __restrict__ Alo,
    const __nv_bfloat16* __restrict__ Bhi, const __nv_bfloat16* __restrict__ Blo,
    const float* __restrict__ bias, float* __restrict__ C,
    int M, int N, int K, int act)
{
    extern __shared__ __align__(16) __nv_bfloat16 smg[];
    __nv_bfloat16* sAhi = smg;                 // [2][CHELEM]
    __nv_bfloat16* sAlo = smg + 2 * CHELEM;
    __nv_bfloat16* sBhi = smg + 4 * CHELEM;
    __nv_bfloat16* sBlo = smg + 6 * CHELEM;

    const int tid  = threadIdx.x;
    const int warp = tid >> 5;
    const int lane = tid & 31;
    const int wr = warp >> 2;
    const int wc = warp & 3;
    const int bm = blockIdx.y * 128;
    const int bn = blockIdx.x * 128;

    const int gid = lane >> 2;
    const int tig = lane & 3;

    float acc[4][4][4];
#pragma unroll
    for (int mt = 0; mt < 4; mt++)
#pragma unroll
        for (int nt = 0; nt < 4; nt++)
#pragma unroll
            for (int q = 0; q < 4; q++) acc[mt][nt][q] = 0.f;

    const int nchunks = K / 32;

    // per-chunk staging: 128 rows x 32 bf16 = 512 x 16B per matrix-half;
    // 2 x 16B per thread per half
    uint4 vah[2], val[2], vbh[2], vbl[2];

    auto ldg_chunk = [&](int ch) {
        const int k0 = ch * 32;
#pragma unroll
        for (int i = 0; i < 2; i++) {
            int f = tid + i * 256;
            int row = f >> 2, q8 = f & 3;
            size_t ga = (size_t)(bm + row) * K + k0 + q8 * 8;
            vah[i] = *reinterpret_cast<const uint4*>(Ahi + ga);
            val[i] = *reinterpret_cast<const uint4*>(Alo + ga);
            vbh[i] = make_uint4(0u, 0u, 0u, 0u);
            vbl[i] = make_uint4(0u, 0u, 0u, 0u);
            if (bn + row < N) {
                size_t gb = (size_t)(bn + row) * K + k0 + q8 * 8;
                vbh[i] = *reinterpret_cast<const uint4*>(Bhi + gb);
                vbl[i] = *reinterpret_cast<const uint4*>(Blo + gb);
            }
        }
    };

    auto stage_chunk = [&](int buf) {
        __nv_bfloat16* dAhi = sAhi + buf * CHELEM;
        __nv_bfloat16* dAlo = sAlo + buf * CHELEM;
        __nv_bfloat16* dBhi = sBhi + buf * CHELEM;
        __nv_bfloat16* dBlo = sBlo + buf * CHELEM;
#pragma unroll
        for (int i = 0; i < 2; i++) {
            int f = tid + i * 256;
            int row = f >> 2, q8 = f & 3;
            int base = row * GSTR + q8 * 8;
            *reinterpret_cast<uint4*>(&dAhi[base]) = vah[i];
            *reinterpret_cast<uint4*>(&dAlo[base]) = val[i];
            *reinterpret_cast<uint4*>(&dBhi[base]) = vbh[i];
            *reinterpret_cast<uint4*>(&dBlo[base]) = vbl[i];
        }
    };

    auto compute_chunk = [&](int buf) {
        const __nv_bfloat16* cAhi = sAhi + buf * CHELEM;
        const __nv_bfloat16* cAlo = sAlo + buf * CHELEM;
        const __nv_bfloat16* cBhi = sBhi + buf * CHELEM;
        const __nv_bfloat16* cBlo = sBlo + buf * CHELEM;
#pragma unroll
        for (int ks = 0; ks < 2; ks++) {
            const int kc = ks * 16 + tig * 2;
            uint32_t bhi[4][2], blo[4][2];
#pragma unroll
            for (int nt = 0; nt < 4; nt++) {
                int n = wc * 32 + nt * 8 + gid;
                bhi[nt][0] = *reinterpret_cast<const uint32_t*>(&cBhi[n * GSTR + kc]);
                bhi[nt][1] = *reinterpret_cast<const uint32_t*>(&cBhi[n * GSTR + kc + 8]);
                blo[nt][0] = *reinterpret_cast<const uint32_t*>(&cBlo[n * GSTR + kc]);
                blo[nt][1] = *reinterpret_cast<const uint32_t*>(&cBlo[n * GSTR + kc + 8]);
            }
#pragma unroll
            for (int mt = 0; mt < 4; mt++) {
                int r = wr * 64 + mt * 16 + gid;
                uint32_t ahi[4], alo[4];
                ahi[0] = *reinterpret_cast<const uint32_t*>(&cAhi[r * GSTR + kc]);
                ahi[1] = *reinterpret_cast<const uint32_t*>(&cAhi[(r + 8) * GSTR + kc]);
                ahi[2] = *reinterpret_cast<const uint32_t*>(&cAhi[r * GSTR + kc + 8]);
                ahi[3] = *reinterpret_cast<const uint32_t*>(&cAhi[(r + 8) * GSTR + kc + 8]);
                alo[0] = *reinterpret_cast<const uint32_t*>(&cAlo[r * GSTR + kc]);
                alo[1] = *reinterpret_cast<const uint32_t*>(&cAlo[(r + 8) * GSTR + kc]);
                alo[2] = *reinterpret_cast<const uint32_t*>(&cAlo[r * GSTR + kc + 8]);
                alo[3] = *reinterpret_cast<const uint32_t*>(&cAlo[(r + 8) * GSTR + kc + 8]);
#pragma unroll
                for (int nt = 0; nt < 4; nt++) {
                    mma_bf16(acc[mt][nt], ahi, bhi[nt]);
                    mma_bf16(acc[mt][nt], ahi, blo[nt]);
                    mma_bf16(acc[mt][nt], alo, bhi[nt]);
                }
            }
        }
    };

    ldg_chunk(0);
    stage_chunk(0);
    __syncthreads();

    for (int ch = 0; ch < nchunks; ch++) {
        if (ch + 1 < nchunks) ldg_chunk(ch + 1);
        compute_chunk(ch & 1);
        if (ch + 1 < nchunks) {
            stage_chunk((ch + 1) & 1);
            __syncthreads();
        }
    }

#pragma unroll
    for (int mt = 0; mt < 4; mt++) {
        int r0 = bm + wr * 64 + mt * 16 + gid;
#pragma unroll
        for (int nt = 0; nt < 4; nt++) {
            int col = bn + wc * 32 + nt * 8 + tig * 2;
            if (col < N) {
                float v0 = acc[mt][nt][0] + bias[col];
                float v1 = acc[mt][nt][1] + bias[col + 1];
                float v2 = acc[mt][nt][2] + bias[col];
                float v3 = acc[mt][nt][3] + bias[col + 1];
                if (act) { v0 = tanhf(v0); v1 = tanhf(v1); v2 = tanhf(v2); v3 = tanhf(v3); }
                float2 o01; o01.x = v0; o01.y = v1;
                float2 o23; o23.x = v2; o23.y = v3;
                *reinterpret_cast<float2*>(&C[(size_t)r0 * N + col]) = o01;
                *reinterpret_cast<float2*>(&C[(size_t)(r0 + 8) * N + col]) = o23;
            }
        }
    }
}

// --------------------------- GRU layer (4-CTA cluster, K-split) -------------
__global__ void __cluster_dims__(4, 1, 1) __launch_bounds__(256, 2) gru_layer(
    const float* __restrict__ xw,    // (NTOK, 960): col = dir*480 + gate*160 + unit
    const float* __restrict__ whh,   // (2, 480, 160)
    const float* __restrict__ bhh,   // (2, 480)
    float* __restrict__ out)         // (NTOK, 320): col = dir*160 + unit
{
    __shared__ __align__(16) float h_s[2][NB][QH];          // own units only
    __shared__ __align__(16) float a_part[2][4][3][QH][NB]; // [buf][sender][gate][u][b]

    const int tid  = threadIdx.x;
    const int rank = blockIdx.x & 3;
    const int c    = blockIdx.x >> 2;
    const int dir  = c & 1;
    const int b0   = (c >> 1) * NB;

    const int g  = (tid < 240) ? (tid / 80) : 0;
    const int j  = tid % 80;
    const int ul = j % 40;
    const int r0 = j / 40;
    const int r1 = 2 + j / 40;

    ull wp0[20], wp1[20];
    if (tid < 240) {
        const int grow0 = dir * 480 + g * 160 + j;
        const int grow1 = dir * 480 + g * 160 + j + 80;
        const float4* w0 = reinterpret_cast<const float4*>(whh + (size_t)grow0 * 160 + rank * QH);
        const float4* w1 = reinterpret_cast<const float4*>(whh + (size_t)grow1 * 160 + rank * QH);
#pragma unroll
        for (int q = 0; q < 10; q++) {
            float4 a = w0[q]; wp0[2 * q] = pk2(a.x, a.y); wp0[2 * q + 1] = pk2(a.z, a.w);
            float4 b = w1[q]; wp1[2 * q] = pk2(b.x, b.y); wp1[2 * q + 1] = pk2(b.z, b.w);
        }
    }

    uint32_t dst0[2], dst1[2];
    if (tid < 240) {
#pragma unroll
        for (int buf = 0; buf < 2; buf++) {
            uint32_t base = (uint32_t)__cvta_generic_to_shared(&a_part[buf][rank][g][ul][0]);
            asm volatile("mapa.shared::cluster.u32 %0, %1, %2;" : "=r"(dst0[buf]) : "r"(base), "r"(r0));
            asm volatile("mapa.shared::cluster.u32 %0, %1, %2;" : "=r"(dst1[buf]) : "r"(base), "r"(r1));
        }
    }

    const int ue = tid % 40;
    const int be = tid / 40;
    const int ug = rank * QH + ue;
    float bh_r = 0.f, bh_z = 0.f, bh_n = 0.f;
    float xr = 0.f, xz = 0.f, xn = 0.f;
    size_t tokb = 0;
    if (tid < 80) {
        bh_r = bhh[dir * 480 + 0 * 160 + ug];
        bh_z = bhh[dir * 480 + 1 * 160 + ug];
        bh_n = bhh[dir * 480 + 2 * 160 + ug];
        tokb = (size_t)(b0 + be) * T_SEQ;
        const int t0 = dir ? (T_SEQ - 1) : 0;
        const float* xp = xw + (tokb + t0) * 960 + dir * 480 + ug;
        xr = xp[0]; xz = xp[160]; xn = xp[320];
    }

    for (int f = tid; f < 2 * NB * QH; f += blockDim.x)
        (&h_s[0][0][0])[f] = 0.f;
    __syncthreads();
    asm volatile("barrier.cluster.arrive.aligned;" ::: "memory");
    asm volatile("barrier.cluster.wait.aligned;" ::: "memory");

    int cur = 0;
    for (int s = 0; s < T_SEQ; s++) {
        const int t = dir ? (T_SEQ - 1 - s) : s;
        const int buf = s & 1;

        if (tid < 240) {
            const ulonglong2* H0 = reinterpret_cast<const ulonglong2*>(&h_s[cur][0][0]);
            const ulonglong2* H1 = reinterpret_cast<const ulonglong2*>(&h_s[cur][1][0]);
            ull a00 = 0ull, a01 = 0ull;
#pragma unroll
            for (int q = 0; q < 10; q++) {
                ulonglong2 hb0 = H0[q];
                ulonglong2 hb1 = H1[q];
                fma2(a00, wp0[2 * q],     hb0.x);
                fma2(a00, wp0[2 * q + 1], hb0.y);
                fma2(a01, wp0[2 * q],     hb1.x);
                fma2(a01, wp0[2 * q + 1], hb1.y);
            }
            ull v0 = pk2(hsum2(a00), hsum2(a01));
            asm volatile("st.shared::cluster.b64 [%0], %1;" :: "r"(dst0[buf]), "l"(v0) : "memory");
            ull a10 = 0ull, a11 = 0ull;
#pragma unroll
            for (int q = 0; q < 10; q++) {
                ulonglong2 hb0 = H0[q];
                ulonglong2 hb1 = H1[q];
                fma2(a10, wp1[2 * q],     hb0.x);
                fma2(a10, wp1[2 * q + 1], hb0.y);
                fma2(a11, wp1[2 * q],     hb1.x);
                fma2(a11, wp1[2 * q + 1], hb1.y);
            }
            ull v1 = pk2(hsum2(a10), hsum2(a11));
            asm volatile("st.shared::cluster.b64 [%0], %1;" :: "r"(dst1[buf]), "l"(v1) : "memory");
        }
        asm volatile("barrier.cluster.arrive.aligned;" ::: "memory");
        asm volatile("barrier.cluster.wait.aligned;" ::: "memory");

        if (tid < 80) {
            float sr = 0.f, sz = 0.f, sn = 0.f;
#pragma unroll
            for (int sd = 0; sd < 4; sd++) {
                sr += a_part[buf][sd][0][ue][be];
                sz += a_part[buf][sd][1][ue][be];
                sn += a_part[buf][sd][2][ue][be];
            }
            float r = 1.f / (1.f + expf(-(xr + sr + bh_r)));
            float z = 1.f / (1.f + expf(-(xz + sz + bh_z)));
            float n = tanhf(xn + r * (sn + bh_n));
            float hp = h_s[cur][be][ue];
            float hnew = (1.f - z) * n + z * hp;
            h_s[cur ^ 1][be][ue] = hnew;
            out[(tokb + t) * 320 + dir * 160 + ug] = hnew;

            if (s + 1 < T_SEQ) {
                const int tn = dir ? (T_SEQ - 2 - s) : (s + 1);
                const float* xp = xw + (tokb + tn) * 960 + dir * 480 + ug;
                xr = xp[0]; xz = xp[160]; xn = xp[320];
            }
        }
        __syncthreads();
        cur ^= 1;
    }

    asm volatile("barrier.cluster.arrive.aligned;" ::: "memory");
    asm volatile("barrier.cluster.wait.aligned;" ::: "memory");
}

// ------------------------------ attention bits -----------------------------
__global__ void __launch_bounds__(256) logits_kernel(
    const float* __restrict__ keys, const float* __restrict__ sw,
    const float* __restrict__ sb, float* __restrict__ logits)
{
    int warp = (blockIdx.x * blockDim.x + threadIdx.x) >> 5;
    int lane = threadIdx.x & 31;
    if (warp >= NTOK) return;
    const float* kr = keys + (size_t)warp * 160;
    float a0 = 0.f, a1 = 0.f, a2 = 0.f, a3 = 0.f;
    for (int k = lane; k < 160; k += 32) {
        float kv = kr[k];
        a0 = fmaf(kv, sw[0 * 160 + k], a0);
        a1 = fmaf(kv, sw[1 * 160 + k], a1);
        a2 = fmaf(kv, sw[2 * 160 + k], a2);
        a3 = fmaf(kv, sw[3 * 160 + k], a3);
    }
#pragma unroll
    for (int off = 16; off; off >>= 1) {
        a0 += __shfl_xor_sync(0xffffffffu, a0, off);
        a1 += __shfl_xor_sync(0xffffffffu, a1, off);
        a2 += __shfl_xor_sync(0xffffffffu, a2, off);
        a3 += __shfl_xor_sync(0xffffffffu, a3, off);
    }
    if (lane == 0) {
        float* o = logits + (size_t)warp * 4;
        o[0] = a0 + sb[0]; o[1] = a1 + sb[1]; o[2] = a2 + sb[2]; o[3] = a3 + sb[3];
    }
}

__global__ void __launch_bounds__(512) motion_kernel(
    const float* __restrict__ x, float* __restrict__ motion)
{
    __shared__ float sd[512];
    __shared__ float red[512];
    int b = blockIdx.x, t = threadIdx.x;
    float d = 0.f;
    if (t >= 1) {
        const float4* r1 = reinterpret_cast<const float4*>(x + ((size_t)b * 512 + t) * 128);
        const float4* r0 = reinterpret_cast<const float4*>(x + ((size_t)b * 512 + t - 1) * 128);
        float acc = 0.f;
#pragma unroll 8
        for (int q = 0; q < 32; q++) {
            float4 a = r1[q], c = r0[q];
            float dx = a.x - c.x, dy = a.y - c.y, dz = a.z - c.z, dw = a.w - c.w;
            acc += dx * dx + dy * dy + dz * dz + dw * dw;
        }
        d = sqrtf(acc);
    }
    sd[t] = d;
    __syncthreads();
    if (t == 0) sd[0] = sd[1];
    __syncthreads();
    d = sd[t];
    red[t] = d; __syncthreads();
    for (int off = 256; off; off >>= 1) { if (t < off) red[t] += red[t + off]; __syncthreads(); }
    float mean = red[0] / 512.f;
    __syncthreads();
    float dd = d - mean;
    red[t] = dd * dd; __syncthreads();
    for (int off = 256; off; off >>= 1) { if (t < off) red[t] += red[t + off]; __syncthreads(); }
    float stdv = sqrtf(red[0] / 511.f);
    motion[(size_t)b * 512 + t] = (d - mean) / (stdv + 1e-6f);
}

__global__ void __launch_bounds__(512) softmax_kernel(
    const float* __restrict__ logits, const float* __restrict__ motion,
    float* __restrict__ wmean_out)
{
    __shared__ float4 red[512];
    int b = blockIdx.x, t = threadIdx.x;
    size_t tok = (size_t)b * 512 + t;
    float4 l = *reinterpret_cast<const float4*>(logits + tok * 4);
    float m = motion[tok];
    l.x += m; l.y += m; l.z += m; l.w += m;
    red[t] = l; __syncthreads();
    for (int off = 256; off; off >>= 1) {
        if (t < off) {
            float4 a = red[t], c = red[t + off];
            a.x = fmaxf(a.x, c.x); a.y = fmaxf(a.y, c.y);
            a.z = fmaxf(a.z, c.z); a.w = fmaxf(a.w, c.w);
            red[t] = a;
        }
        __syncthreads();
    }
    float4 mx = red[0];
    __syncthreads();
    float4 e;
    e.x = expf(l.x - mx.x); e.y = expf(l.y - mx.y);
    e.z = expf(l.z - mx.z); e.w = expf(l.w - mx.w);
    red[t] = e; __syncthreads();
    for (int off = 256; off; off >>= 1) {
        if (t < off) {
            float4 a = red[t], c = red[t + off];
            a.x += c.x; a.y += c.y; a.z += c.z; a.w += c.w;
            red[t] = a;
        }
        __syncthreads();
    }
    float4 s = red[0];
    wmean_out[tok] = 0.25f * (e.x / s.x + e.y / s.y + e.z / s.z + e.w / s.w);
}

__global__ void __launch_bounds__(320) pool_kernel(
    const float* __restrict__ seq, const float* __restrict__ wm,
    float* __restrict__ pooled)
{
    __shared__ float sw[512];
    int b = blockIdx.x, d = threadIdx.x;
    for (int i = d; i < 512; i += 320) sw[i] = wm[(size_t)b * 512 + i];
    __syncthreads();
    float acc = 0.f;
    const float* sp = seq + (size_t)b * 512 * 320 + d;
#pragma unroll 8
    for (int t = 0; t < 512; t++) acc = fmaf(sp[(size_t)t * 320], sw[t], acc);
    pooled[b * 320 + d] = acc;
}

__global__ void __launch_bounds__(256) final_kernel(
    const float* __restrict__ pooled, const float* __restrict__ pw,
    const float* __restrict__ pb, const float* __restrict__ lng,
    const float* __restrict__ lnb, float* __restrict__ out)
{
    __shared__ float sp[320];
    __shared__ float red[256];
    int b = blockIdx.x, e = threadIdx.x;
    for (int i = e; i < 320; i += 256) sp[i] = pooled[b * 320 + i];
    __syncthreads();
    float acc = 0.f;
    const float* wr = pw + (size_t)e * 320;
#pragma unroll 4
    for (int k = 0; k < 320; k += 4) {
        acc = fmaf(wr[k + 0], sp[k + 0], acc);
        acc = fmaf(wr[k + 1], sp[k + 1], acc);
        acc = fmaf(wr[k + 2], sp[k + 2], acc);
        acc = fmaf(wr[k + 3], sp[k + 3], acc);
    }
    acc += pb[e];
    red[e] = acc; __syncthreads();
    for (int off = 128; off; off >>= 1) { if (e < off) red[e] += red[e + off]; __syncthreads(); }
    float mean = red[0] / 256.f;
    __syncthreads();
    float dd = acc - mean;
    red[e] = dd * dd; __syncthreads();
    for (int off = 128; off; off >>= 1) { if (e < off) red[e] += red[e + off]; __syncthreads(); }
    float var = red[0] / 256.f;
    __syncthreads();
    float v = dd * rsqrtf(var + 1e-5f) * lng[e] + lnb[e];
    red[e] = v * v; __syncthreads();
    for (int off = 128; off; off >>= 1) { if (e < off) red[e] += red[e + off]; __syncthreads(); }
    float nrm = fmaxf(sqrtf(red[0]), 1e-12f);
    out[b * 256 + e] = v / nrm;
}

// ------------------------------- launch -------------------------------------
extern "C" void kernel_launch(void* const* d_in, const int* in_sizes, int n_in,
                              void* d_out, int out_size)
{
    const float* x       = (const float*)d_in[0];
    const float* Wih0    = (const float*)d_in[1];
    const float* Whh0    = (const float*)d_in[2];
    const float* bih0    = (const float*)d_in[3];
    const float* bhh0    = (const float*)d_in[4];
    const float* Wih1    = (const float*)d_in[5];
    const float* Whh1    = (const float*)d_in[6];
    const float* bih1    = (const float*)d_in[7];
    const float* bhh1    = (const float*)d_in[8];
    const float* key_w   = (const float*)d_in[9];
    const float* key_b   = (const float*)d_in[10];
    const float* score_w = (const float*)d_in[11];
    const float* score_b = (const float*)d_in[12];
    const float* proj_w  = (const float*)d_in[13];
    const float* proj_b  = (const float*)d_in[14];
    const float* ln_g    = (const float*)d_in[15];
    const float* ln_b    = (const float*)d_in[16];
    float* out = (float*)d_out;
    float* out_emb = out;            // (64, 256)
    float* out_wm  = out + 64 * 256; // (64, 512)

    float *xw, *h1, *seq, *keys, *logits, *motion, *pooled;
    __nv_bfloat16 *ahi, *alo, *whi, *wlo;
    cudaGetSymbolAddress((void**)&xw,     g_xw);
    cudaGetSymbolAddress((void**)&h1,     g_h1);
    cudaGetSymbolAddress((void**)&seq,    g_seq);
    cudaGetSymbolAddress((void**)&keys,   g_keys);
    cudaGetSymbolAddress((void**)&logits, g_logits);
    cudaGetSymbolAddress((void**)&motion, g_motion);
    cudaGetSymbolAddress((void**)&pooled, g_pooled);
    cudaGetSymbolAddress((void**)&ahi,    g_ahi);
    cudaGetSymbolAddress((void**)&alo,    g_alo);
    cudaGetSymbolAddress((void**)&whi,    g_whi);
    cudaGetSymbolAddress((void**)&wlo,    g_wlo);

    cudaFuncSetAttribute(mma_gemm_bias, cudaFuncAttributeMaxDynamicSharedMemorySize, GEMM_SMEM);

    // independent prep: motion + all weight splits
    motion_kernel<<<BATCH, 512>>>(x, motion);
    split_kernel<<<(960 * 128 / 4 + 255) / 256, 256>>>(
        (const float4*)Wih0, (uint2*)(whi + OFF_W0), (uint2*)(wlo + OFF_W0), 960 * 128 / 4);
    split_kernel<<<(960 * 320 / 4 + 255) / 256, 256>>>(
        (const float4*)Wih1, (uint2*)(whi + OFF_W1), (uint2*)(wlo + OFF_W1), 960 * 320 / 4);
    split_kernel<<<(160 * 320 / 4 + 255) / 256, 256>>>(
        (const float4*)key_w, (uint2*)(whi + OFF_KW), (uint2*)(wlo + OFF_KW), 160 * 320 / 4);

    // layer 0: split x, GEMM (K=128), GRU
    split_kernel<<<(NTOK * 128 / 4 + 255) / 256, 256>>>(
        (const float4*)x, (uint2*)ahi, (uint2*)alo, NTOK * 128 / 4);
    mma_gemm_bias<<<dim3(8, NTOK / 128), 256, GEMM_SMEM>>>(
        ahi, alo, whi + OFF_W0, wlo + OFF_W0, bih0, xw, NTOK, 960, 128, 0);
    gru_layer<<<256, 256>>>(xw, Whh0, bhh0, h1);

    // layer 1: split h1, GEMM (K=320), GRU
    split_kernel<<<(NTOK * 320 / 4 + 255) / 256, 256>>>(
        (const float4*)h1, (uint2*)ahi, (uint2*)alo, NTOK * 320 / 4);
    mma_gemm_bias<<<dim3(8, NTOK / 128), 256, GEMM_SMEM>>>(
        ahi, alo, whi + OFF_W1, wlo + OFF_W1, bih1, xw, NTOK, 960, 320, 0);
    gru_layer<<<256, 256>>>(xw, Whh1, bhh1, seq);

    // keys = tanh(seq @ key_w^T + key_b): split seq, GEMM (N=160, K=320)
    split_kernel<<<(NTOK * 320 / 4 + 255) / 256, 256>>>(
        (const float4*)seq, (uint2*)ahi, (uint2*)alo, NTOK * 320 / 4);
    mma_gemm_bias<<<dim3(2, NTOK / 128), 256, GEMM_SMEM>>>(
        ahi, alo, whi + OFF_KW, wlo + OFF_KW, key_b, keys, NTOK, 160, 320, 1);

    // attention logits, softmax over T (writes weights.mean to out_wm)
    logits_kernel<<<NTOK / 8, 256>>>(keys, score_w, score_b, logits);
    softmax_kernel<<<BATCH, 512>>>(logits, motion, out_wm);

    // pooled + projection + LN + L2 norm
    pool_kernel<<<BATCH, 320>>>(seq, out_wm, pooled);
    final_kernel<<<BATCH, 256>>>(pooled, proj_w, proj_b, ln_g, ln_b, out_emb);
}

// round 15
// speedup vs baseline: 1.0388x; 1.0388x over previous
#include <cuda_runtime.h>
#include <cuda_bf16.h>
#include <cstdint>
#include <cstddef>

#define T_SEQ 512
#define BATCH 64
#define NTOK  (BATCH * T_SEQ)   // 32768
#define NB 2                    // batches per GRU cluster
#define QH 40                   // hidden units / k-range per CTA (160/4)

typedef unsigned long long ull;

// ---- packed f32x2 helpers (sm_103a FFMA2 path) -----------------------------
__device__ __forceinline__ void fma2(ull& d, ull a, ull b) {
    asm("fma.rn.f32x2 %0, %1, %2, %0;" : "+l"(d) : "l"(a), "l"(b));
}
__device__ __forceinline__ ull pk2(float lo, float hi) {
    ull d; asm("mov.b64 %0, {%1, %2};" : "=l"(d) : "f"(lo), "f"(hi)); return d;
}
__device__ __forceinline__ float2 upk2(ull v) {
    float2 r; asm("mov.b64 {%0, %1}, %2;" : "=f"(r.x), "=f"(r.y) : "l"(v)); return r;
}
__device__ __forceinline__ float hsum2(ull v) {
    float2 e = upk2(v); return e.x + e.y;
}

// ----------------------------- scratch ------------------------------------
__device__ float g_xw[(size_t)NTOK * 960];
__device__ float g_h1[(size_t)NTOK * 320];
__device__ float g_seq[(size_t)NTOK * 320];
__device__ float g_keys[(size_t)NTOK * 160];
__device__ float g_logits[(size_t)NTOK * 4];
__device__ float g_motion[NTOK];
__device__ float g_pooled[BATCH * 320];

// bf16 hi/lo buffers for the three weight matrices (B operands only)
#define OFF_W0 0
#define OFF_W1 (960 * 128)
#define OFF_KW (960 * 128 + 960 * 320)
#define W_TOTAL (960 * 128 + 960 * 320 + 160 * 320)
__device__ __nv_bfloat16 g_whi[W_TOTAL];
__device__ __nv_bfloat16 g_wlo[W_TOTAL];

// -------------------- fp32 -> bf16 hi/lo split kernel ----------------------
__global__ void __launch_bounds__(256) split_kernel(
    const float4* __restrict__ src, uint2* __restrict__ hi,
    uint2* __restrict__ lo, int n4)
{
    int i = blockIdx.x * blockDim.x + threadIdx.x;
    if (i >= n4) return;
    float4 v = src[i];
    __nv_bfloat16 hx = __float2bfloat16(v.x), hy = __float2bfloat16(v.y);
    __nv_bfloat16 hz = __float2bfloat16(v.z), hw = __float2bfloat16(v.w);
    __nv_bfloat16 lx = __float2bfloat16(v.x - __bfloat162float(hx));
    __nv_bfloat16 ly = __float2bfloat16(v.y - __bfloat162float(hy));
    __nv_bfloat16 lz = __float2bfloat16(v.z - __bfloat162float(hz));
    __nv_bfloat16 lw = __float2bfloat16(v.w - __bfloat162float(hw));
    __nv_bfloat162 h01; h01.x = hx; h01.y = hy;
    __nv_bfloat162 h23; h23.x = hz; h23.y = hw;
    __nv_bfloat162 l01; l01.x = lx; l01.y = ly;
    __nv_bfloat162 l23; l23.x = lz; l23.y = lw;
    uint2 ho, loo;
    ho.x  = *reinterpret_cast<uint32_t*>(&h01);
    ho.y  = *reinterpret_cast<uint32_t*>(&h23);
    loo.x = *reinterpret_cast<uint32_t*>(&l01);
    loo.y = *reinterpret_cast<uint32_t*>(&l23);
    hi[i] = ho;
    lo[i] = loo;
}

// ================= HMMA (mma.sync) bf16-compensated GEMM ===================
// A fp32 (converted inline once per N-tile pass); B pre-split bf16 hi/lo.
// C = Ahi*Bhi + Ahi*Blo + Alo*Bhi + bias (+tanh)
// CTA tile 128x128, 8 warps (2x4) of 64x32 warp tiles, K chunked by 32,
// double-buffered smem staging.

#define GSTR 40               // bf16 elements per smem row (80B stride)
#define CHELEM (128 * GSTR)   // 5120 bf16 per array per buffer
#define GEMM_SMEM (8 * CHELEM * (int)sizeof(__nv_bfloat16))   // 81920 B

__device__ __forceinline__ void mma_bf16(float* c, const uint32_t* a, const uint32_t* b) {
    asm volatile(
        "mma.sync.aligned.m16n8k16.row.col.f32.bf16.bf16.f32 "
        "{%0,%1,%2,%3}, {%4,%5,%6,%7}, {%8,%9}, {%0,%1,%2,%3};"
        : "+f"(c[0]), "+f"(c[1]), "+f"(c[2]), "+f"(c[3])
        : "r"(a[0]), "r"(a[1]), "r"(a[2]), "r"(a[3]), "r"(b[0]), "r"(b[1]));
}

__global__ void __launch_bounds__(256, 2) mma_gemm_bias(
    const float* __restrict__ A,
    const __nv_bfloat16* __restrict__ Bhi, const __nv_bfloat16* __restrict__ Blo,
    const float* __restrict__ bias, float* __restrict__ C,
    int M, int N, int K, int act)
{
    extern __shared__ __align__(16) __nv_bfloat16 smg[];
    __nv_bfloat16* sAhi = smg;                 // [2][CHELEM]
    __nv_bfloat16* sAlo = smg + 2 * CHELEM;
    __nv_bfloat16* sBhi = smg + 4 * CHELEM;
    __nv_bfloat16* sBlo = smg + 6 * CHELEM;

    const int tid  = threadIdx.x;
    const int warp = tid >> 5;
    const int lane = tid & 31;
    const int wr = warp >> 2;
    const int wc = warp & 3;
    const int bm = blockIdx.y * 128;
    const int bn = blockIdx.x * 128;

    const int gid = lane >> 2;
    const int tig = lane & 3;

    float acc[4][4][4];
#pragma unroll
    for (int mt = 0; mt < 4; mt++)
#pragma unroll
        for (int nt = 0; nt < 4; nt++)
#pragma unroll
            for (int q = 0; q < 4; q++) acc[mt][nt][q] = 0.f;

    const int nchunks = K / 32;

    float4 va[4];            // A: 4 float4 per thread (128x32 fp32)
    uint4 vbh[2], vbl[2];    // B: 2 uint4 per thread per half (128x32 bf16)

    auto ldg_chunk = [&](int ch) {
        const int k0 = ch * 32;
#pragma unroll
        for (int i = 0; i < 4; i++) {
            int f = tid + i * 256;
            int row = f >> 3, q = f & 7;
            va[i] = *reinterpret_cast<const float4*>(A + (size_t)(bm + row) * K + k0 + q * 4);
        }
#pragma unroll
        for (int i = 0; i < 2; i++) {
            int f = tid + i * 256;
            int row = f >> 2, q8 = f & 3;
            vbh[i] = make_uint4(0u, 0u, 0u, 0u);
            vbl[i] = make_uint4(0u, 0u, 0u, 0u);
            if (bn + row < N) {
                size_t gb = (size_t)(bn + row) * K + k0 + q8 * 8;
                vbh[i] = *reinterpret_cast<const uint4*>(Bhi + gb);
                vbl[i] = *reinterpret_cast<const uint4*>(Blo + gb);
            }
        }
    };

    auto stage_chunk = [&](int buf) {
        __nv_bfloat16* dAhi = sAhi + buf * CHELEM;
        __nv_bfloat16* dAlo = sAlo + buf * CHELEM;
        __nv_bfloat16* dBhi = sBhi + buf * CHELEM;
        __nv_bfloat16* dBlo = sBlo + buf * CHELEM;
#pragma unroll
        for (int i = 0; i < 4; i++) {
            int f = tid + i * 256;
            int row = f >> 3, q = f & 7;
            int base = row * GSTR + q * 4;
            float4 v = va[i];
            __nv_bfloat16 hx = __float2bfloat16(v.x), hy = __float2bfloat16(v.y);
            __nv_bfloat16 hz = __float2bfloat16(v.z), hw = __float2bfloat16(v.w);
            __nv_bfloat16 lx = __float2bfloat16(v.x - __bfloat162float(hx));
            __nv_bfloat16 ly = __float2bfloat16(v.y - __bfloat162float(hy));
            __nv_bfloat16 lz = __float2bfloat16(v.z - __bfloat162float(hz));
            __nv_bfloat16 lw = __float2bfloat16(v.w - __bfloat162float(hw));
            __nv_bfloat162 h01; h01.x = hx; h01.y = hy;
            __nv_bfloat162 h23; h23.x = hz; h23.y = hw;
            __nv_bfloat162 l01; l01.x = lx; l01.y = ly;
            __nv_bfloat162 l23; l23.x = lz; l23.y = lw;
            *reinterpret_cast<__nv_bfloat162*>(&dAhi[base])     = h01;
            *reinterpret_cast<__nv_bfloat162*>(&dAhi[base + 2]) = h23;
            *reinterpret_cast<__nv_bfloat162*>(&dAlo[base])     = l01;
            *reinterpret_cast<__nv_bfloat162*>(&dAlo[base + 2]) = l23;
        }
#pragma unroll
        for (int i = 0; i < 2; i++) {
            int f = tid + i * 256;
            int row = f >> 2, q8 = f & 3;
            int base = row * GSTR + q8 * 8;
            *reinterpret_cast<uint4*>(&dBhi[base]) = vbh[i];
            *reinterpret_cast<uint4*>(&dBlo[base]) = vbl[i];
        }
    };

    auto compute_chunk = [&](int buf) {
        const __nv_bfloat16* cAhi = sAhi + buf * CHELEM;
        const __nv_bfloat16* cAlo = sAlo + buf * CHELEM;
        const __nv_bfloat16* cBhi = sBhi + buf * CHELEM;
        const __nv_bfloat16* cBlo = sBlo + buf * CHELEM;
#pragma unroll
        for (int ks = 0; ks < 2; ks++) {
            const int kc = ks * 16 + tig * 2;
            uint32_t bhi[4][2], blo[4][2];
#pragma unroll
            for (int nt = 0; nt < 4; nt++) {
                int n = wc * 32 + nt * 8 + gid;
                bhi[nt][0] = *reinterpret_cast<const uint32_t*>(&cBhi[n * GSTR + kc]);
                bhi[nt][1] = *reinterpret_cast<const uint32_t*>(&cBhi[n * GSTR + kc + 8]);
                blo[nt][0] = *reinterpret_cast<const uint32_t*>(&cBlo[n * GSTR + kc]);
                blo[nt][1] = *reinterpret_cast<const uint32_t*>(&cBlo[n * GSTR + kc + 8]);
            }
#pragma unroll
            for (int mt = 0; mt < 4; mt++) {
                int r = wr * 64 + mt * 16 + gid;
                uint32_t ahi[4], alo[4];
                ahi[0] = *reinterpret_cast<const uint32_t*>(&cAhi[r * GSTR + kc]);
                ahi[1] = *reinterpret_cast<const uint32_t*>(&cAhi[(r + 8) * GSTR + kc]);
                ahi[2] = *reinterpret_cast<const uint32_t*>(&cAhi[r * GSTR + kc + 8]);
                ahi[3] = *reinterpret_cast<const uint32_t*>(&cAhi[(r + 8) * GSTR + kc + 8]);
                alo[0] = *reinterpret_cast<const uint32_t*>(&cAlo[r * GSTR + kc]);
                alo[1] = *reinterpret_cast<const uint32_t*>(&cAlo[(r + 8) * GSTR + kc]);
                alo[2] = *reinterpret_cast<const uint32_t*>(&cAlo[r * GSTR + kc + 8]);
                alo[3] = *reinterpret_cast<const uint32_t*>(&cAlo[(r + 8) * GSTR + kc + 8]);
#pragma unroll
                for (int nt = 0; nt < 4; nt++) {
                    mma_bf16(acc[mt][nt], ahi, bhi[nt]);
                    mma_bf16(acc[mt][nt], ahi, blo[nt]);
                    mma_bf16(acc[mt][nt], alo, bhi[nt]);
                }
            }
        }
    };

    ldg_chunk(0);
    stage_chunk(0);
    __syncthreads();

    for (int ch = 0; ch < nchunks; ch++) {
        if (ch + 1 < nchunks) ldg_chunk(ch + 1);
        compute_chunk(ch & 1);
        if (ch + 1 < nchunks) {
            stage_chunk((ch + 1) & 1);
            __syncthreads();
        }
    }

#pragma unroll
    for (int mt = 0; mt < 4; mt++) {
        int r0 = bm + wr * 64 + mt * 16 + gid;
#pragma unroll
        for (int nt = 0; nt < 4; nt++) {
            int col = bn + wc * 32 + nt * 8 + tig * 2;
            if (col < N) {
                float v0 = acc[mt][nt][0] + bias[col];
                float v1 = acc[mt][nt][1] + bias[col + 1];
                float v2 = acc[mt][nt][2] + bias[col];
                float v3 = acc[mt][nt][3] + bias[col + 1];
                if (act) { v0 = tanhf(v0); v1 = tanhf(v1); v2 = tanhf(v2); v3 = tanhf(v3); }
                float2 o01; o01.x = v0; o01.y = v1;
                float2 o23; o23.x = v2; o23.y = v3;
                *reinterpret_cast<float2*>(&C[(size_t)r0 * N + col]) = o01;
                *reinterpret_cast<float2*>(&C[(size_t)(r0 + 8) * N + col]) = o23;
            }
        }
    }
}

// --------------------------- GRU layer (4-CTA cluster, K-split) -------------
__global__ void __cluster_dims__(4, 1, 1) __launch_bounds__(256, 2) gru_layer(
    const float* __restrict__ xw,    // (NTOK, 960): col = dir*480 + gate*160 + unit
    const float* __restrict__ whh,   // (2, 480, 160)
    const float* __restrict__ bhh,   // (2, 480)
    float* __restrict__ out)         // (NTOK, 320): col = dir*160 + unit
{
    __shared__ __align__(16) float h_s[2][NB][QH];          // own units only
    __shared__ __align__(16) float a_part[2][4][3][QH][NB]; // [buf][sender][gate][u][b]

    const int tid  = threadIdx.x;
    const int rank = blockIdx.x & 3;
    const int c    = blockIdx.x >> 2;
    const int dir  = c & 1;
    const int b0   = (c >> 1) * NB;

    const int g  = (tid < 240) ? (tid / 80) : 0;
    const int j  = tid % 80;
    const int ul = j % 40;
    const int r0 = j / 40;
    const int r1 = 2 + j / 40;

    ull wp0[20], wp1[20];
    if (tid < 240) {
        const int grow0 = dir * 480 + g * 160 + j;
        const int grow1 = dir * 480 + g * 160 + j + 80;
        const float4* w0 = reinterpret_cast<const float4*>(whh + (size_t)grow0 * 160 + rank * QH);
        const float4* w1 = reinterpret_cast<const float4*>(whh + (size_t)grow1 * 160 + rank * QH);
#pragma unroll
        for (int q = 0; q < 10; q++) {
            float4 a = w0[q]; wp0[2 * q] = pk2(a.x, a.y); wp0[2 * q + 1] = pk2(a.z, a.w);
            float4 b = w1[q]; wp1[2 * q] = pk2(b.x, b.y); wp1[2 * q + 1] = pk2(b.z, b.w);
        }
    }

    uint32_t dst0[2], dst1[2];
    if (tid < 240) {
#pragma unroll
        for (int buf = 0; buf < 2; buf++) {
            uint32_t base = (uint32_t)__cvta_generic_to_shared(&a_part[buf][rank][g][ul][0]);
            asm volatile("mapa.shared::cluster.u32 %0, %1, %2;" : "=r"(dst0[buf]) : "r"(base), "r"(r0));
            asm volatile("mapa.shared::cluster.u32 %0, %1, %2;" : "=r"(dst1[buf]) : "r"(base), "r"(r1));
        }
    }

    const int ue = tid % 40;
    const int be = tid / 40;
    const int ug = rank * QH + ue;
    float bh_r = 0.f, bh_z = 0.f, bh_n = 0.f;
    float xr = 0.f, xz = 0.f, xn = 0.f;
    size_t tokb = 0;
    if (tid < 80) {
        bh_r = bhh[dir * 480 + 0 * 160 + ug];
        bh_z = bhh[dir * 480 + 1 * 160 + ug];
        bh_n = bhh[dir * 480 + 2 * 160 + ug];
        tokb = (size_t)(b0 + be) * T_SEQ;
        const int t0 = dir ? (T_SEQ - 1) : 0;
        const float* xp = xw + (tokb + t0) * 960 + dir * 480 + ug;
        xr = xp[0]; xz = xp[160]; xn = xp[320];
    }

    for (int f = tid; f < 2 * NB * QH; f += blockDim.x)
        (&h_s[0][0][0])[f] = 0.f;
    __syncthreads();
    asm volatile("barrier.cluster.arrive.aligned;" ::: "memory");
    asm volatile("barrier.cluster.wait.aligned;" ::: "memory");

    int cur = 0;
    for (int s = 0; s < T_SEQ; s++) {
        const int t = dir ? (T_SEQ - 1 - s) : s;
        const int buf = s & 1;

        if (tid < 240) {
            const ulonglong2* H0 = reinterpret_cast<const ulonglong2*>(&h_s[cur][0][0]);
            const ulonglong2* H1 = reinterpret_cast<const ulonglong2*>(&h_s[cur][1][0]);
            ull a00 = 0ull, a01 = 0ull;
#pragma unroll
            for (int q = 0; q < 10; q++) {
                ulonglong2 hb0 = H0[q];
                ulonglong2 hb1 = H1[q];
                fma2(a00, wp0[2 * q],     hb0.x);
                fma2(a00, wp0[2 * q + 1], hb0.y);
                fma2(a01, wp0[2 * q],     hb1.x);
                fma2(a01, wp0[2 * q + 1], hb1.y);
            }
            ull v0 = pk2(hsum2(a00), hsum2(a01));
            asm volatile("st.shared::cluster.b64 [%0], %1;" :: "r"(dst0[buf]), "l"(v0) : "memory");
            ull a10 = 0ull, a11 = 0ull;
#pragma unroll
            for (int q = 0; q < 10; q++) {
                ulonglong2 hb0 = H0[q];
                ulonglong2 hb1 = H1[q];
                fma2(a10, wp1[2 * q],     hb0.x);
                fma2(a10, wp1[2 * q + 1], hb0.y);
                fma2(a11, wp1[2 * q],     hb1.x);
                fma2(a11, wp1[2 * q + 1], hb1.y);
            }
            ull v1 = pk2(hsum2(a10), hsum2(a11));
            asm volatile("st.shared::cluster.b64 [%0], %1;" :: "r"(dst1[buf]), "l"(v1) : "memory");
        }
        asm volatile("barrier.cluster.arrive.aligned;" ::: "memory");
        asm volatile("barrier.cluster.wait.aligned;" ::: "memory");

        if (tid < 80) {
            float sr = 0.f, sz = 0.f, sn = 0.f;
#pragma unroll
            for (int sd = 0; sd < 4; sd++) {
                sr += a_part[buf][sd][0][ue][be];
                sz += a_part[buf][sd][1][ue][be];
                sn += a_part[buf][sd][2][ue][be];
            }
            float r = 1.f / (1.f + expf(-(xr + sr + bh_r)));
            float z = 1.f / (1.f + expf(-(xz + sz + bh_z)));
            float n = tanhf(xn + r * (sn + bh_n));
            float hp = h_s[cur][be][ue];
            float hnew = (1.f - z) * n + z * hp;
            h_s[cur ^ 1][be][ue] = hnew;
            out[(tokb + t) * 320 + dir * 160 + ug] = hnew;

            if (s + 1 < T_SEQ) {
                const int tn = dir ? (T_SEQ - 2 - s) : (s + 1);
                const float* xp = xw + (tokb + tn) * 960 + dir * 480 + ug;
                xr = xp[0]; xz = xp[160]; xn = xp[320];
            }
        }
        __syncthreads();
        cur ^= 1;
    }

    asm volatile("barrier.cluster.arrive.aligned;" ::: "memory");
    asm volatile("barrier.cluster.wait.aligned;" ::: "memory");
}

// ------------------------------ attention bits -----------------------------
__global__ void __launch_bounds__(256) logits_kernel(
    const float* __restrict__ keys, const float* __restrict__ sw,
    const float* __restrict__ sb, float* __restrict__ logits)
{
    int warp = (blockIdx.x * blockDim.x + threadIdx.x) >> 5;
    int lane = threadIdx.x & 31;
    if (warp >= NTOK) return;
    const float* kr = keys + (size_t)warp * 160;
    float a0 = 0.f, a1 = 0.f, a2 = 0.f, a3 = 0.f;
    for (int k = lane; k < 160; k += 32) {
        float kv = kr[k];
        a0 = fmaf(kv, sw[0 * 160 + k], a0);
        a1 = fmaf(kv, sw[1 * 160 + k], a1);
        a2 = fmaf(kv, sw[2 * 160 + k], a2);
        a3 = fmaf(kv, sw[3 * 160 + k], a3);
    }
#pragma unroll
    for (int off = 16; off; off >>= 1) {
        a0 += __shfl_xor_sync(0xffffffffu, a0, off);
        a1 += __shfl_xor_sync(0xffffffffu, a1, off);
        a2 += __shfl_xor_sync(0xffffffffu, a2, off);
        a3 += __shfl_xor_sync(0xffffffffu, a3, off);
    }
    if (lane == 0) {
        float* o = logits + (size_t)warp * 4;
        o[0] = a0 + sb[0]; o[1] = a1 + sb[1]; o[2] = a2 + sb[2]; o[3] = a3 + sb[3];
    }
}

__global__ void __launch_bounds__(512) motion_kernel(
    const float* __restrict__ x, float* __restrict__ motion)
{
    __shared__ float sd[512];
    __shared__ float red[512];
    int b = blockIdx.x, t = threadIdx.x;
    float d = 0.f;
    if (t >= 1) {
        const float4* r1 = reinterpret_cast<const float4*>(x + ((size_t)b * 512 + t) * 128);
        const float4* r0 = reinterpret_cast<const float4*>(x + ((size_t)b * 512 + t - 1) * 128);
        float acc = 0.f;
#pragma unroll 8
        for (int q = 0; q < 32; q++) {
            float4 a = r1[q], c = r0[q];
            float dx = a.x - c.x, dy = a.y - c.y, dz = a.z - c.z, dw = a.w - c.w;
            acc += dx * dx + dy * dy + dz * dz + dw * dw;
        }
        d = sqrtf(acc);
    }
    sd[t] = d;
    __syncthreads();
    if (t == 0) sd[0] = sd[1];
    __syncthreads();
    d = sd[t];
    red[t] = d; __syncthreads();
    for (int off = 256; off; off >>= 1) { if (t < off) red[t] += red[t + off]; __syncthreads(); }
    float mean = red[0] / 512.f;
    __syncthreads();
    float dd = d - mean;
    red[t] = dd * dd; __syncthreads();
    for (int off = 256; off; off >>= 1) { if (t < off) red[t] += red[t + off]; __syncthreads(); }
    float stdv = sqrtf(red[0] / 511.f);
    motion[(size_t)b * 512 + t] = (d - mean) / (stdv + 1e-6f);
}

__global__ void __launch_bounds__(512) softmax_kernel(
    const float* __restrict__ logits, const float* __restrict__ motion,
    float* __restrict__ wmean_out)
{
    __shared__ float4 red[512];
    int b = blockIdx.x, t = threadIdx.x;
    size_t tok = (size_t)b * 512 + t;
    float4 l = *reinterpret_cast<const float4*>(logits + tok * 4);
    float m = motion[tok];
    l.x += m; l.y += m; l.z += m; l.w += m;
    red[t] = l; __syncthreads();
    for (int off = 256; off; off >>= 1) {
        if (t < off) {
            float4 a = red[t], c = red[t + off];
            a.x = fmaxf(a.x, c.x); a.y = fmaxf(a.y, c.y);
            a.z = fmaxf(a.z, c.z); a.w = fmaxf(a.w, c.w);
            red[t] = a;
        }
        __syncthreads();
    }
    float4 mx = red[0];
    __syncthreads();
    float4 e;
    e.x = expf(l.x - mx.x); e.y = expf(l.y - mx.y);
    e.z = expf(l.z - mx.z); e.w = expf(l.w - mx.w);
    red[t] = e; __syncthreads();
    for (int off = 256; off; off >>= 1) {
        if (t < off) {
            float4 a = red[t], c = red[t + off];
            a.x += c.x; a.y += c.y; a.z += c.z; a.w += c.w;
            red[t] = a;
        }
        __syncthreads();
    }
    float4 s = red[0];
    wmean_out[tok] = 0.25f * (e.x / s.x + e.y / s.y + e.z / s.z + e.w / s.w);
}

__global__ void __launch_bounds__(320) pool_kernel(
    const float* __restrict__ seq, const float* __restrict__ wm,
    float* __restrict__ pooled)
{
    __shared__ float sw[512];
    int b = blockIdx.x, d = threadIdx.x;
    for (int i = d; i < 512; i += 320) sw[i] = wm[(size_t)b * 512 + i];
    __syncthreads();
    float acc = 0.f;
    const float* sp = seq + (size_t)b * 512 * 320 + d;
#pragma unroll 8
    for (int t = 0; t < 512; t++) acc = fmaf(sp[(size_t)t * 320], sw[t], acc);
    pooled[b * 320 + d] = acc;
}

__global__ void __launch_bounds__(256) final_kernel(
    const float* __restrict__ pooled, const float* __restrict__ pw,
    const float* __restrict__ pb, const float* __restrict__ lng,
    const float* __restrict__ lnb, float* __restrict__ out)
{
    __shared__ float sp[320];
    __shared__ float red[256];
    int b = blockIdx.x, e = threadIdx.x;
    for (int i = e; i < 320; i += 256) sp[i] = pooled[b * 320 + i];
    __syncthreads();
    float acc = 0.f;
    const float* wr = pw + (size_t)e * 320;
#pragma unroll 4
    for (int k = 0; k < 320; k += 4) {
        acc = fmaf(wr[k + 0], sp[k + 0], acc);
        acc = fmaf(wr[k + 1], sp[k + 1], acc);
        acc = fmaf(wr[k + 2], sp[k + 2], acc);
        acc = fmaf(wr[k + 3], sp[k + 3], acc);
    }
    acc += pb[e];
    red[e] = acc; __syncthreads();
    for (int off = 128; off; off >>= 1) { if (e < off) red[e] += red[e + off]; __syncthreads(); }
    float mean = red[0] / 256.f;
    __syncthreads();
    float dd = acc - mean;
    red[e] = dd * dd; __syncthreads();
    for (int off = 128; off; off >>= 1) { if (e < off) red[e] += red[e + off]; __syncthreads(); }
    float var = red[0] / 256.f;
    __syncthreads();
    float v = dd * rsqrtf(var + 1e-5f) * lng[e] + lnb[e];
    red[e] = v * v; __syncthreads();
    for (int off = 128; off; off >>= 1) { if (e < off) red[e] += red[e + off]; __syncthreads(); }
    float nrm = fmaxf(sqrtf(red[0]), 1e-12f);
    out[b * 256 + e] = v / nrm;
}

// ------------------------------- launch -------------------------------------
extern "C" void kernel_launch(void* const* d_in, const int* in_sizes, int n_in,
                              void* d_out, int out_size)
{
    const float* x       = (const float*)d_in[0];
    const float* Wih0    = (const float*)d_in[1];
    const float* Whh0    = (const float*)d_in[2];
    const float* bih0    = (const float*)d_in[3];
    const float* bhh0    = (const float*)d_in[4];
    const float* Wih1    = (const float*)d_in[5];
    const float* Whh1    = (const float*)d_in[6];
    const float* bih1    = (const float*)d_in[7];
    const float* bhh1    = (const float*)d_in[8];
    const float* key_w   = (const float*)d_in[9];
    const float* key_b   = (const float*)d_in[10];
    const float* score_w = (const float*)d_in[11];
    const float* score_b = (const float*)d_in[12];
    const float* proj_w  = (const float*)d_in[13];
    const float* proj_b  = (const float*)d_in[14];
    const float* ln_g    = (const float*)d_in[15];
    const float* ln_b    = (const float*)d_in[16];
    float* out = (float*)d_out;
    float* out_emb = out;            // (64, 256)
    float* out_wm  = out + 64 * 256; // (64, 512)

    float *xw, *h1, *seq, *keys, *logits, *motion, *pooled;
    __nv_bfloat16 *whi, *wlo;
    cudaGetSymbolAddress((void**)&xw,     g_xw);
    cudaGetSymbolAddress((void**)&h1,     g_h1);
    cudaGetSymbolAddress((void**)&seq,    g_seq);
    cudaGetSymbolAddress((void**)&keys,   g_keys);
    cudaGetSymbolAddress((void**)&logits, g_logits);
    cudaGetSymbolAddress((void**)&motion, g_motion);
    cudaGetSymbolAddress((void**)&pooled, g_pooled);
    cudaGetSymbolAddress((void**)&whi,    g_whi);
    cudaGetSymbolAddress((void**)&wlo,    g_wlo);

    cudaFuncSetAttribute(mma_gemm_bias, cudaFuncAttributeMaxDynamicSharedMemorySize, GEMM_SMEM);

    // independent prep: motion + weight splits (small, cheap)
    motion_kernel<<<BATCH, 512>>>(x, motion);
    split_kernel<<<(960 * 128 / 4 + 255) / 256, 256>>>(
        (const float4*)Wih0, (uint2*)(whi + OFF_W0), (uint2*)(wlo + OFF_W0), 960 * 128 / 4);
    split_kernel<<<(960 * 320 / 4 + 255) / 256, 256>>>(
        (const float4*)Wih1, (uint2*)(whi + OFF_W1), (uint2*)(wlo + OFF_W1), 960 * 320 / 4);
    split_kernel<<<(160 * 320 / 4 + 255) / 256, 256>>>(
        (const float4*)key_w, (uint2*)(whi + OFF_KW), (uint2*)(wlo + OFF_KW), 160 * 320 / 4);

    // layer 0: GEMM (K=128) + GRU
    mma_gemm_bias<<<dim3(8, NTOK / 128), 256, GEMM_SMEM>>>(
        x, whi + OFF_W0, wlo + OFF_W0, bih0, xw, NTOK, 960, 128, 0);
    gru_layer<<<256, 256>>>(xw, Whh0, bhh0, h1);

    // layer 1: GEMM (K=320) + GRU
    mma_gemm_bias<<<dim3(8, NTOK / 128), 256, GEMM_SMEM>>>(
        h1, whi + OFF_W1, wlo + OFF_W1, bih1, xw, NTOK, 960, 320, 0);
    gru_layer<<<256, 256>>>(xw, Whh1, bhh1, seq);

    // keys = tanh(seq @ key_w^T + key_b)  (N=160, K=320)
    mma_gemm_bias<<<dim3(2, NTOK / 128), 256, GEMM_SMEM>>>(
        seq, whi + OFF_KW, wlo + OFF_KW, key_b, keys, NTOK, 160, 320, 1);

    // attention logits, softmax over T (writes weights.mean to out_wm)
    logits_kernel<<<NTOK / 8, 256>>>(keys, score_w, score_b, logits);
    softmax_kernel<<<BATCH, 512>>>(logits, motion, out_wm);

    // pooled + projection + LN + L2 norm
    pool_kernel<<<BATCH, 320>>>(seq, out_wm, pooled);
    final_kernel<<<BATCH, 256>>>(pooled, proj_w, proj_b, ln_g, ln_b, out_emb);
}